// round 10
// baseline (speedup 1.0000x reference)
#include <cuda_runtime.h>
#include <cuda_fp16.h>
#include <cstdint>
#include <cstddef>

#define E_TOTAL 400000
#define DIM 128
#define G_TOTAL 512
#define BM 128
#define NTHREADS 256
#define SSTR 136                         // halves; 272B rows -> conflict-free ldmatrix
#define CHUNK_HALVES (DIM * SSTR)        // 17408 halves = 34816 B per image
#define IMG_BYTES (CHUNK_HALVES * 2)     // 34816 B
#define SMEM_BYTES (6 * IMG_BYTES)       // 2 A buffers + 4 resident W images = 208896 B

// Scratch (static device arrays allowed; allocation is not)
__device__ float  g_UB[G_TOTAL * DIM];                    // u @ W1[384:512] + b1 (fp32 exact)
__device__ __align__(16) __half g_W[4 * CHUNK_HALVES];    // fp16 weights, [chunk][n][k] stride 136
__device__ int    g_batch[E_TOTAL];

__device__ __forceinline__ void cp_async16(uint32_t dst_smem, const void* src) {
    asm volatile("cp.async.cg.shared.global [%0], [%1], 16;\n" :: "r"(dst_smem), "l"(src));
}
__device__ __forceinline__ void cp_async_commit() {
    asm volatile("cp.async.commit_group;\n" ::: "memory");
}
__device__ __forceinline__ void cp_async_wait0() {
    asm volatile("cp.async.wait_group 0;\n" ::: "memory");
}
__device__ __forceinline__ void ldsm4(unsigned& r0, unsigned& r1, unsigned& r2, unsigned& r3,
                                      uint32_t addr) {
    asm volatile("ldmatrix.sync.aligned.m8n8.x4.shared.b16 {%0,%1,%2,%3}, [%4];"
                 : "=r"(r0), "=r"(r1), "=r"(r2), "=r"(r3) : "r"(addr));
}
__device__ __forceinline__ void mma16816(float* c, const unsigned* a, unsigned b0, unsigned b1) {
    asm volatile(
        "mma.sync.aligned.m16n8k16.row.col.f32.f16.f16.f32 "
        "{%0,%1,%2,%3},{%4,%5,%6,%7},{%8,%9},{%0,%1,%2,%3};\n"
        : "+f"(c[0]), "+f"(c[1]), "+f"(c[2]), "+f"(c[3])
        : "r"(a[0]), "r"(a[1]), "r"(a[2]), "r"(a[3]), "r"(b0), "r"(b1));
}

// ---------------------------------------------------------------------------
// batch may arrive as int32 (JAX x64 disabled) or int64 (see R1 notes).
// ---------------------------------------------------------------------------
__global__ void batch_norm_kernel(const int* __restrict__ bp32) {
    bool is64 = (bp32[E_TOTAL - 1] == 0);
    int i = blockIdx.x * blockDim.x + threadIdx.x;
    if (i < E_TOTAL)
        g_batch[i] = is64 ? (int)(((const long long*)bp32)[i]) : bp32[i];
}

// UB[g][n] = b1[n] + sum_k u[g][k] * W1[384+k][n]   (exact fp32, tiny)
__global__ void ub_kernel(const float* __restrict__ u, const float* __restrict__ W1,
                          const float* __restrict__ b1) {
    __shared__ float us[DIM];
    int gi = blockIdx.x, n = threadIdx.x;
    us[n] = u[gi * DIM + n];
    __syncthreads();
    float acc = b1[n];
    const float* w = W1 + 3 * DIM * DIM + n;
#pragma unroll 8
    for (int k = 0; k < DIM; ++k) acc += us[k] * w[k * DIM];
    g_UB[gi * DIM + n] = acc;
}

// One-time weight transform: chunk c<3 -> W1 K-rows [c*128,c*128+128); c=3 -> W2.
// Image [n][k] halves, stride 136 (pads stay 0 in bss).
__global__ void wconv_kernel(const float* __restrict__ W1, const float* __restrict__ W2) {
    int c = blockIdx.x, n = blockIdx.y, k = threadIdx.x;
    float v = (c < 3) ? W1[(c * DIM + k) * DIM + n] : W2[k * DIM + n];
    g_W[c * CHUNK_HALVES + n * SSTR + k] = __float2half_rn(v);
}

// 8 k16-steps over a K=128 chunk via ldmatrix + mma.m16n8k16.
// aB/bB are per-lane base addresses into buffer 0 / W image 0; offsets select
// the active A buffer and W chunk.
__device__ __forceinline__ void mma_block(const uint32_t aB[2], const uint32_t bB[4],
                                          uint32_t aOff, uint32_t bOff,
                                          float acc[2][8][4]) {
#pragma unroll
    for (int ks = 0; ks < 8; ++ks) {
        const uint32_t ko = ks * 32;          // 16 halves = 32 bytes
        unsigned a[2][4];
        ldsm4(a[0][0], a[0][1], a[0][2], a[0][3], aB[0] + aOff + ko);
        ldsm4(a[1][0], a[1][1], a[1][2], a[1][3], aB[1] + aOff + ko);
#pragma unroll
        for (int p = 0; p < 4; ++p) {
            unsigned b0, b1, b2, b3;
            ldsm4(b0, b1, b2, b3, bB[p] + bOff + ko);
            mma16816(acc[0][2 * p + 0], a[0], b0, b1);
            mma16816(acc[0][2 * p + 1], a[0], b2, b3);
            mma16816(acc[1][2 * p + 0], a[1], b0, b1);
            mma16816(acc[1][2 * p + 1], a[1], b2, b3);
        }
    }
}

// Load one 128x128 fp32 chunk into registers (16 float4 / thread).
__device__ __forceinline__ void ldg_chunk(const float* __restrict__ Ap, int e0, int tid,
                                          float4 pf[16]) {
#pragma unroll
    for (int it = 0; it < 16; ++it) {
        int i = it * NTHREADS + tid;
        int row = i >> 5, c4 = (i & 31) << 2;
        pf[it] = *reinterpret_cast<const float4*>(Ap + (size_t)(e0 + row) * DIM + c4);
    }
}

// Convert to fp16 + store into an A buffer. Warp writes one row -> conflict-free.
__device__ __forceinline__ void sts_chunk(__half* __restrict__ sA, int tid,
                                          const float4 pf[16]) {
#pragma unroll
    for (int it = 0; it < 16; ++it) {
        int i = it * NTHREADS + tid;
        int row = i >> 5, c4 = (i & 31) << 2;
        __half2 h0 = __floats2half2_rn(pf[it].x, pf[it].y);
        __half2 h1 = __floats2half2_rn(pf[it].z, pf[it].w);
        *reinterpret_cast<__half2*>(sA + row * SSTR + c4) = h0;
        *reinterpret_cast<__half2*>(sA + row * SSTR + c4 + 2) = h1;
    }
}

__global__ __launch_bounds__(NTHREADS, 1)
void edge_mlp_kernel(const float* __restrict__ src, const float* __restrict__ dst,
                     const float* __restrict__ edge,
                     const float* __restrict__ b2, float* __restrict__ out) {
    extern __shared__ __half smem_h[];
    // layout: [A buf0][A buf1][W0][W1][W2][W3], each CHUNK_HALVES halves
    __half* sA0 = smem_h;
    const uint32_t sA_u32 = (uint32_t)__cvta_generic_to_shared(smem_h);
    const uint32_t sW_u32 = sA_u32 + 2 * IMG_BYTES;

    const int tid = threadIdx.x;
    const int warp = tid >> 5, lane = tid & 31;
    const int wm = warp & 3, wn = warp >> 2;
    const int g = lane >> 2, tg = lane & 3;
    const int e0 = blockIdx.x * BM;

    // per-lane ldmatrix base addresses (bytes, shared space), buffer-0 relative
    const int q = lane >> 3, rr = lane & 7;
    uint32_t aB[2], bB[4];
#pragma unroll
    for (int mi = 0; mi < 2; ++mi) {
        int row = wm * 32 + mi * 16 + rr + (q & 1) * 8;
        int kof = (q >> 1) * 8;
        aB[mi] = sA_u32 + (row * SSTR + kof) * 2;
    }
#pragma unroll
    for (int p = 0; p < 4; ++p) {
        int n = wn * 64 + p * 16 + rr + (q >> 1) * 8;
        int kof = (q & 1) * 8;
        bB[p] = sW_u32 + (n * SSTR + kof) * 2;
    }

    float acc[2][8][4];
#pragma unroll
    for (int mi = 0; mi < 2; ++mi)
#pragma unroll
        for (int ni = 0; ni < 8; ++ni)
#pragma unroll
            for (int j = 0; j < 4; ++j) acc[mi][ni][j] = 0.f;

    const float* parts[3] = {src, dst, edge};
    float4 pf[16];

    // ---------------- prologue ----------------
    ldg_chunk(parts[0], e0, tid, pf);           // A0 -> regs
    // all 4 weight images -> smem once (linear, conflict-free, async)
    {
        const char* wsrc = (const char*)g_W;
#pragma unroll
        for (int t = 0; t < 34; ++t) {          // 8704 16B units / 256 threads
            int i = t * NTHREADS + tid;
            cp_async16(sW_u32 + i * 16, wsrc + (size_t)i * 16);
        }
        cp_async_commit();
    }
    sts_chunk(sA0, tid, pf);                    // A0 -> buf0
    ldg_chunk(parts[1], e0, tid, pf);           // prefetch A1
    cp_async_wait0();
    __syncthreads();

    // ---------------- layer 1: three K=128 chunks, pipelined ----------------
#pragma unroll 1
    for (int j = 0; j < 3; ++j) {
        // stage next chunk into the other buffer; issue the following LDGs.
        // These have no dependency on the MMA stream below -> they drain in
        // the tensor phase's shadow.
        if (j < 2) {
            sts_chunk(smem_h + ((j + 1) & 1) * CHUNK_HALVES, tid, pf);
            if (j < 1) ldg_chunk(parts[2], e0, tid, pf);
        }
        mma_block(aB, bB, (j & 1) * IMG_BYTES, j * IMG_BYTES, acc);
        __syncthreads();   // publishes buf (j+1)&1, frees buf j&1
    }

    // ------ epilogue 1: + UB[batch] gather, relu, H -> buf1 (fp16) ------
    // (last mma read buf0; buf1 free since the j=1 sync)
    {
        __half* sH = smem_h + CHUNK_HALVES;
#pragma unroll
        for (int mi = 0; mi < 2; ++mi) {
            const int rA = wm * 32 + mi * 16 + g;
            const int rB = rA + 8;
            const int ga = g_batch[e0 + rA];
            const int gb = g_batch[e0 + rB];
#pragma unroll
            for (int ni = 0; ni < 8; ++ni) {
                const int c = wn * 64 + ni * 8 + tg * 2;
                float2 ua = *reinterpret_cast<const float2*>(g_UB + (size_t)ga * DIM + c);
                float2 ub = *reinterpret_cast<const float2*>(g_UB + (size_t)gb * DIM + c);
                float h0 = fmaxf(acc[mi][ni][0] + ua.x, 0.f);
                float h1 = fmaxf(acc[mi][ni][1] + ua.y, 0.f);
                float h2 = fmaxf(acc[mi][ni][2] + ub.x, 0.f);
                float h3 = fmaxf(acc[mi][ni][3] + ub.y, 0.f);
                *reinterpret_cast<__half2*>(sH + rA * SSTR + c) = __floats2half2_rn(h0, h1);
                *reinterpret_cast<__half2*>(sH + rB * SSTR + c) = __floats2half2_rn(h2, h3);
            }
        }
    }

    // reset accumulators for layer 2
#pragma unroll
    for (int mi = 0; mi < 2; ++mi)
#pragma unroll
        for (int ni = 0; ni < 8; ++ni)
#pragma unroll
            for (int j = 0; j < 4; ++j) acc[mi][ni][j] = 0.f;

    __syncthreads();                            // H visible to all warps

    // ---------------- layer 2: out = H(buf1) @ W2(image 3) ----------------
    mma_block(aB, bB, 1 * IMG_BYTES, 3 * IMG_BYTES, acc);

    // ---------------- epilogue 2: + b2, fp32 store ----------------
#pragma unroll
    for (int mi = 0; mi < 2; ++mi) {
        const int rA = wm * 32 + mi * 16 + g;
        const int rB = rA + 8;
#pragma unroll
        for (int ni = 0; ni < 8; ++ni) {
            const int c = wn * 64 + ni * 8 + tg * 2;
            float2 bv = *reinterpret_cast<const float2*>(b2 + c);
            *reinterpret_cast<float2*>(out + (size_t)(e0 + rA) * DIM + c) =
                make_float2(acc[mi][ni][0] + bv.x, acc[mi][ni][1] + bv.y);
            *reinterpret_cast<float2*>(out + (size_t)(e0 + rB) * DIM + c) =
                make_float2(acc[mi][ni][2] + bv.x, acc[mi][ni][3] + bv.y);
        }
    }
}

extern "C" void kernel_launch(void* const* d_in, const int* in_sizes, int n_in,
                              void* d_out, int out_size) {
    const float* src  = (const float*)d_in[0];
    const float* dst  = (const float*)d_in[1];
    const float* edge = (const float*)d_in[2];
    const float* u    = (const float*)d_in[3];
    const int*   bat  = (const int*)d_in[4];
    const float* W1   = (const float*)d_in[5];
    const float* b1   = (const float*)d_in[6];
    const float* W2   = (const float*)d_in[7];
    const float* b2   = (const float*)d_in[8];
    float* out = (float*)d_out;
    (void)in_sizes; (void)n_in; (void)out_size;

    cudaFuncSetAttribute(edge_mlp_kernel,
                         cudaFuncAttributeMaxDynamicSharedMemorySize, SMEM_BYTES);

    batch_norm_kernel<<<(E_TOTAL + 255) / 256, 256>>>(bat);
    ub_kernel<<<G_TOTAL, DIM>>>(u, W1, b1);
    wconv_kernel<<<dim3(4, DIM), DIM>>>(W1, W2);
    edge_mlp_kernel<<<E_TOTAL / BM, NTHREADS, SMEM_BYTES>>>(src, dst, edge, b2, out);
}

// round 11
// speedup vs baseline: 1.2164x; 1.2164x over previous
#include <cuda_runtime.h>
#include <cuda_fp16.h>
#include <cstdint>
#include <cstddef>

#define E_TOTAL 400000
#define DIM 128
#define G_TOTAL 512
#define BM 128
#define NTHREADS 256
#define SSTR 136                         // halves; 272B rows -> conflict-free ldmatrix
#define CHUNK_HALVES (DIM * SSTR)        // 17408 halves = 34816 B per image
#define IMG_BYTES (CHUNK_HALVES * 2)     // 34816 B
#define SMEM_BYTES (4 * IMG_BYTES)       // A0,A1,Wbuf0,Wbuf1 = 139264 B

// Scratch (static device arrays allowed; allocation is not)
__device__ float  g_UB[G_TOTAL * DIM];                    // u @ W1[384:512] + b1 (fp32 exact)
__device__ __align__(16) __half g_W[4 * CHUNK_HALVES];    // fp16 weights, [chunk][n][k] stride 136
__device__ int    g_batch[E_TOTAL];

__device__ __forceinline__ void cp_async16(uint32_t dst_smem, const void* src) {
    asm volatile("cp.async.cg.shared.global [%0], [%1], 16;\n" :: "r"(dst_smem), "l"(src));
}
__device__ __forceinline__ void cp_async_commit() {
    asm volatile("cp.async.commit_group;\n" ::: "memory");
}
__device__ __forceinline__ void cp_async_wait0() {
    asm volatile("cp.async.wait_group 0;\n" ::: "memory");
}
__device__ __forceinline__ void ldsm4(unsigned& r0, unsigned& r1, unsigned& r2, unsigned& r3,
                                      uint32_t addr) {
    asm volatile("ldmatrix.sync.aligned.m8n8.x4.shared.b16 {%0,%1,%2,%3}, [%4];"
                 : "=r"(r0), "=r"(r1), "=r"(r2), "=r"(r3) : "r"(addr));
}
__device__ __forceinline__ void mma16816(float* c, const unsigned* a, unsigned b0, unsigned b1) {
    asm volatile(
        "mma.sync.aligned.m16n8k16.row.col.f32.f16.f16.f32 "
        "{%0,%1,%2,%3},{%4,%5,%6,%7},{%8,%9},{%0,%1,%2,%3};\n"
        : "+f"(c[0]), "+f"(c[1]), "+f"(c[2]), "+f"(c[3])
        : "r"(a[0]), "r"(a[1]), "r"(a[2]), "r"(a[3]), "r"(b0), "r"(b1));
}

// ---------------------------------------------------------------------------
// batch may arrive as int32 (JAX x64 disabled) or int64 (see R1 notes).
// ---------------------------------------------------------------------------
__global__ void batch_norm_kernel(const int* __restrict__ bp32) {
    bool is64 = (bp32[E_TOTAL - 1] == 0);
    int i = blockIdx.x * blockDim.x + threadIdx.x;
    if (i < E_TOTAL)
        g_batch[i] = is64 ? (int)(((const long long*)bp32)[i]) : bp32[i];
}

// UB[g][n] = b1[n] + sum_k u[g][k] * W1[384+k][n]   (exact fp32, tiny)
__global__ void ub_kernel(const float* __restrict__ u, const float* __restrict__ W1,
                          const float* __restrict__ b1) {
    __shared__ float us[DIM];
    int gi = blockIdx.x, n = threadIdx.x;
    us[n] = u[gi * DIM + n];
    __syncthreads();
    float acc = b1[n];
    const float* w = W1 + 3 * DIM * DIM + n;
#pragma unroll 8
    for (int k = 0; k < DIM; ++k) acc += us[k] * w[k * DIM];
    g_UB[gi * DIM + n] = acc;
}

// One-time weight transform: chunk c<3 -> W1 K-rows [c*128,c*128+128); c=3 -> W2.
// Image [n][k] halves, stride 136 (pads stay 0 in bss).
__global__ void wconv_kernel(const float* __restrict__ W1, const float* __restrict__ W2) {
    int c = blockIdx.x, n = blockIdx.y, k = threadIdx.x;
    float v = (c < 3) ? W1[(c * DIM + k) * DIM + n] : W2[k * DIM + n];
    g_W[c * CHUNK_HALVES + n * SSTR + k] = __float2half_rn(v);
}

// Stage weight image c into W slot (async copy, caller commits).
__device__ __forceinline__ void cp_wimg(uint32_t wslot_u32, int c, int tid) {
    const char* wsrc = (const char*)(g_W + (size_t)c * CHUNK_HALVES);
#pragma unroll
    for (int it = 0; it < 9; ++it) {
        int i = it * NTHREADS + tid;           // 16B unit
        if (i < IMG_BYTES / 16)
            cp_async16(wslot_u32 + i * 16, wsrc + (size_t)i * 16);
    }
    cp_async_commit();
}

// 8 k16-steps over a K=128 chunk via ldmatrix + mma.m16n8k16.
__device__ __forceinline__ void mma_block(const uint32_t aB[2], const uint32_t bB[4],
                                          uint32_t aOff, uint32_t bOff,
                                          float acc[2][8][4]) {
#pragma unroll
    for (int ks = 0; ks < 8; ++ks) {
        const uint32_t ko = ks * 32;           // 16 halves = 32 bytes
        unsigned a[2][4];
        ldsm4(a[0][0], a[0][1], a[0][2], a[0][3], aB[0] + aOff + ko);
        ldsm4(a[1][0], a[1][1], a[1][2], a[1][3], aB[1] + aOff + ko);
#pragma unroll
        for (int p = 0; p < 4; ++p) {
            unsigned b0, b1, b2, b3;
            ldsm4(b0, b1, b2, b3, bB[p] + bOff + ko);
            mma16816(acc[0][2 * p + 0], a[0], b0, b1);
            mma16816(acc[0][2 * p + 1], a[0], b2, b3);
            mma16816(acc[1][2 * p + 0], a[1], b0, b1);
            mma16816(acc[1][2 * p + 1], a[1], b2, b3);
        }
    }
}

// Load one 128x128 fp32 chunk into registers (16 float4 / thread).
__device__ __forceinline__ void ldg_chunk(const float* __restrict__ Ap, int e0, int tid,
                                          float4 pf[16]) {
#pragma unroll
    for (int it = 0; it < 16; ++it) {
        int i = it * NTHREADS + tid;
        int row = i >> 5, c4 = (i & 31) << 2;
        pf[it] = *reinterpret_cast<const float4*>(Ap + (size_t)(e0 + row) * DIM + c4);
    }
}

// Convert to fp16 + store into an A buffer. Warp writes one row -> conflict-free.
__device__ __forceinline__ void sts_chunk(__half* __restrict__ sA, int tid,
                                          const float4 pf[16]) {
#pragma unroll
    for (int it = 0; it < 16; ++it) {
        int i = it * NTHREADS + tid;
        int row = i >> 5, c4 = (i & 31) << 2;
        __half2 h0 = __floats2half2_rn(pf[it].x, pf[it].y);
        __half2 h1 = __floats2half2_rn(pf[it].z, pf[it].w);
        *reinterpret_cast<__half2*>(sA + row * SSTR + c4) = h0;
        *reinterpret_cast<__half2*>(sA + row * SSTR + c4 + 2) = h1;
    }
}

__global__ __launch_bounds__(NTHREADS, 1)
void edge_mlp_kernel(const float* __restrict__ src, const float* __restrict__ dst,
                     const float* __restrict__ edge,
                     const float* __restrict__ b2, float* __restrict__ out) {
    extern __shared__ __half smem_h[];
    // layout: [A buf0][A buf1][W slot0][W slot1], each CHUNK_HALVES halves
    const uint32_t sA_u32 = (uint32_t)__cvta_generic_to_shared(smem_h);
    const uint32_t sW_u32 = sA_u32 + 2 * IMG_BYTES;

    const int tid = threadIdx.x;
    const int warp = tid >> 5, lane = tid & 31;
    const int wm = warp & 3, wn = warp >> 2;
    const int g = lane >> 2, tg = lane & 3;
    const int e0 = blockIdx.x * BM;

    // per-lane ldmatrix base addresses (bytes, shared space), slot-0 relative
    const int q = lane >> 3, rr = lane & 7;
    uint32_t aB[2], bB[4];
#pragma unroll
    for (int mi = 0; mi < 2; ++mi) {
        int row = wm * 32 + mi * 16 + rr + (q & 1) * 8;
        int kof = (q >> 1) * 8;
        aB[mi] = sA_u32 + (row * SSTR + kof) * 2;
    }
#pragma unroll
    for (int p = 0; p < 4; ++p) {
        int n = wn * 64 + p * 16 + rr + (q >> 1) * 8;
        int kof = (q & 1) * 8;
        bB[p] = sW_u32 + (n * SSTR + kof) * 2;
    }

    float acc[2][8][4];
#pragma unroll
    for (int mi = 0; mi < 2; ++mi)
#pragma unroll
        for (int ni = 0; ni < 8; ++ni)
#pragma unroll
            for (int j = 0; j < 4; ++j) acc[mi][ni][j] = 0.f;

    const float* parts[3] = {src, dst, edge};
    float4 pf[16];

    // ---------------- prologue ----------------
    ldg_chunk(parts[0], e0, tid, pf);           // A0 -> regs
    cp_wimg(sW_u32, 0, tid);                    // W0 -> slot0 (async)
    sts_chunk(smem_h, tid, pf);                 // A0 -> buf0
    ldg_chunk(parts[1], e0, tid, pf);           // prefetch A1
    cp_async_wait0();
    __syncthreads();

    // ------------- layer 1: three K=128 chunks, fully pipelined -------------
#pragma unroll 1
    for (int j = 0; j < 3; ++j) {
        // prefetch next weight image into the other W slot (W3 at j==2 for layer 2)
        cp_wimg(sW_u32 + (((j + 1) & 1) ? IMG_BYTES : 0), j + 1, tid);
        // stage next A chunk into the other A buffer; issue following LDGs
        if (j < 2) {
            sts_chunk(smem_h + ((j + 1) & 1) * CHUNK_HALVES, tid, pf);
            if (j < 1) ldg_chunk(parts[2], e0, tid, pf);
        }
        // MMA on current buffers — copies above drain in its shadow
        mma_block(aB, bB, (j & 1) * IMG_BYTES, (j & 1) * IMG_BYTES, acc);
        cp_async_wait0();      // next W image landed (had the whole MMA phase)
        __syncthreads();       // publish next A buf + W slot; free current ones
    }

    // ------ epilogue 1: + UB[batch] gather, relu, H -> A buf1 (fp16) ------
    // (last mma read buf0; buf1 free since the j=1 barrier)
    {
        __half* sH = smem_h + CHUNK_HALVES;
#pragma unroll
        for (int mi = 0; mi < 2; ++mi) {
            const int rA = wm * 32 + mi * 16 + g;
            const int rB = rA + 8;
            const int ga = g_batch[e0 + rA];
            const int gb = g_batch[e0 + rB];
#pragma unroll
            for (int ni = 0; ni < 8; ++ni) {
                const int c = wn * 64 + ni * 8 + tg * 2;
                float2 ua = *reinterpret_cast<const float2*>(g_UB + (size_t)ga * DIM + c);
                float2 ub = *reinterpret_cast<const float2*>(g_UB + (size_t)gb * DIM + c);
                float h0 = fmaxf(acc[mi][ni][0] + ua.x, 0.f);
                float h1 = fmaxf(acc[mi][ni][1] + ua.y, 0.f);
                float h2 = fmaxf(acc[mi][ni][2] + ub.x, 0.f);
                float h3 = fmaxf(acc[mi][ni][3] + ub.y, 0.f);
                *reinterpret_cast<__half2*>(sH + rA * SSTR + c) = __floats2half2_rn(h0, h1);
                *reinterpret_cast<__half2*>(sH + rB * SSTR + c) = __floats2half2_rn(h2, h3);
            }
        }
    }

    // reset accumulators for layer 2
#pragma unroll
    for (int mi = 0; mi < 2; ++mi)
#pragma unroll
        for (int ni = 0; ni < 8; ++ni)
#pragma unroll
            for (int j = 0; j < 4; ++j) acc[mi][ni][j] = 0.f;

    __syncthreads();                            // H visible to all warps

    // ------- layer 2: out = H(A buf1) @ W2(W slot1, prefetched at j=2) -------
    mma_block(aB, bB, 1 * IMG_BYTES, 1 * IMG_BYTES, acc);

    // ---------------- epilogue 2: + b2, fp32 store ----------------
#pragma unroll
    for (int mi = 0; mi < 2; ++mi) {
        const int rA = wm * 32 + mi * 16 + g;
        const int rB = rA + 8;
#pragma unroll
        for (int ni = 0; ni < 8; ++ni) {
            const int c = wn * 64 + ni * 8 + tg * 2;
            float2 bv = *reinterpret_cast<const float2*>(b2 + c);
            *reinterpret_cast<float2*>(out + (size_t)(e0 + rA) * DIM + c) =
                make_float2(acc[mi][ni][0] + bv.x, acc[mi][ni][1] + bv.y);
            *reinterpret_cast<float2*>(out + (size_t)(e0 + rB) * DIM + c) =
                make_float2(acc[mi][ni][2] + bv.x, acc[mi][ni][3] + bv.y);
        }
    }
}

extern "C" void kernel_launch(void* const* d_in, const int* in_sizes, int n_in,
                              void* d_out, int out_size) {
    const float* src  = (const float*)d_in[0];
    const float* dst  = (const float*)d_in[1];
    const float* edge = (const float*)d_in[2];
    const float* u    = (const float*)d_in[3];
    const int*   bat  = (const int*)d_in[4];
    const float* W1   = (const float*)d_in[5];
    const float* b1   = (const float*)d_in[6];
    const float* W2   = (const float*)d_in[7];
    const float* b2   = (const float*)d_in[8];
    float* out = (float*)d_out;
    (void)in_sizes; (void)n_in; (void)out_size;

    cudaFuncSetAttribute(edge_mlp_kernel,
                         cudaFuncAttributeMaxDynamicSharedMemorySize, SMEM_BYTES);

    batch_norm_kernel<<<(E_TOTAL + 255) / 256, 256>>>(bat);
    ub_kernel<<<G_TOTAL, DIM>>>(u, W1, b1);
    wconv_kernel<<<dim3(4, DIM), DIM>>>(W1, W2);
    edge_mlp_kernel<<<E_TOTAL / BM, NTHREADS, SMEM_BYTES>>>(src, dst, edge, b2, out);
}